// round 8
// baseline (speedup 1.0000x reference)
#include <cuda_runtime.h>

// Problem constants (B, S, K) = (512, 2048, 17)
#define BB 512
#define SS 2048
#define KK 17
#define SK (SS * KK)
#define CHUNKS 16
#define CL 128
#define TSTEPS 16
#define TILEF (TSTEPS * KK)     // 272 floats per 16-step tile
#define NCOPY_BLOCKS 512
#define SCAN_WPB 4
#define NPAIRS (BB * CHUNKS / 2)          // 4096 packed warps
#define NSCAN_BLOCKS (NPAIRS / SCAN_WPB)  // 1024

__device__ float g_part2[BB * CHUNKS];

__device__ __forceinline__ void cp16(void* smem, const void* gmem) {
    unsigned s = (unsigned)__cvta_generic_to_shared(smem);
    asm volatile("cp.async.cg.shared.global [%0], [%1], 16;\n" :: "r"(s), "l"(gmem));
}
#define CP_COMMIT() asm volatile("cp.async.commit_group;\n" ::: "memory")
#define CP_WAIT1()  asm volatile("cp.async.wait_group 1;\n" ::: "memory")

// one 272-float tile (68 x 16B) global -> shared via cp.async
__device__ __forceinline__ void load_tile(float* dst, const float* src, int lane) {
    cp16(dst + lane * 4,        src + lane * 4);
    cp16(dst + (32 + lane) * 4, src + (32 + lane) * 4);
    if (lane < 4)
        cp16(dst + (64 + lane) * 4, src + (64 + lane) * 4);
}

typedef unsigned long long ull;

__device__ __forceinline__ ull f32x2_fma(ull a, ull b, ull c) {
    ull d;
    asm("fma.rn.f32x2 %0, %1, %2, %3;" : "=l"(d) : "l"(a), "l"(b), "l"(c));
    return d;
}
__device__ __forceinline__ ull packf2(float lo, float hi) {
    return ((ull)__float_as_uint(hi) << 32) | (ull)__float_as_uint(lo);
}
__device__ __forceinline__ float lof(ull u) { return __uint_as_float((unsigned)u); }
__device__ __forceinline__ float hif(ull u) { return __uint_as_float((unsigned)(u >> 32)); }

__global__ __launch_bounds__(128) void crf_kernel(
    const float* __restrict__ em,      // [B,S,K]
    const float* __restrict__ startT,  // [K]
    const float* __restrict__ endT,    // [K]
    const float* __restrict__ trans,   // [K,K]
    const int*   __restrict__ labels,  // [B,S]
    const int*   __restrict__ attn,    // [B,S]
    float* __restrict__ out,           // [0]=loss, [1..]=emissions copy
    int copy_emissions)
{
    // ======== copy blocks: rotated, vectorized both sides ========
    if (blockIdx.x < NCOPY_BLOCKS) {
        if (!copy_emissions) return;
        const size_t base = (size_t)blockIdx.x * SK;
        const float4* s4 = (const float4*)(em + base);
        float* dst = out + 1 + base;           // dst+3 is 16B-aligned
        const int n4 = (SK - 4) / 4;           // 8703 aligned float4 stores
        for (int j = threadIdx.x; j < n4; j += 128) {
            float4 x = s4[j];
            float4 y = s4[j + 1];              // overlapping load: L1 hit
            *(float4*)(dst + 3 + 4 * j) = make_float4(x.w, y.x, y.y, y.z);
        }
        if (threadIdx.x == 0) {
            float4 x0 = s4[0];
            dst[0] = x0.x; dst[1] = x0.y; dst[2] = x0.z;
            dst[SK - 1] = em[base + SK - 1];
        }
        return;
    }

    // ======== scan blocks: each warp = one chunk PAIR (2p, 2p+1) ========
    const int tid  = threadIdx.x;
    const int wid  = tid >> 5;
    const int lane = tid & 31;
    const int gw   = (blockIdx.x - NCOPY_BLOCKS) * SCAN_WPB + wid;
    const int b    = gw >> 3;                  // 8 pairs per sequence
    const int p    = gw & 7;
    const int cA   = 2 * p, cB = 2 * p + 1;

    const float* emb = em + (size_t)b * SK;
    const int*   lab = labels + (size_t)b * SS;
    const int*   msk = attn   + (size_t)b * SS;

    __shared__ __align__(16) float ebuf[SCAN_WPB][2][2][TILEF];
    __shared__ __align__(16) float arow[SCAN_WPB][2][64];

    // activity (mask is a prefix)
    bool activeA = (p == 0) || ((msk[cA * CL] != 0) && (lab[cA * CL] >= 0));
    if (!activeA) {
        if (lane == 0) {
            g_part2[b * CHUNKS + cA] = 0.0f;
            g_part2[b * CHUNKS + cB] = 0.0f;
        }
        return;
    }
    bool activeB    = (msk[cB * CL] != 0) && (lab[cB * CL] >= 0);
    bool activeNext = (p < 7) ? ((msk[(cB + 1) * CL] != 0) && (lab[(cB + 1) * CL] >= 0)) : false;
    const bool containsA = !activeB;
    const bool containsB = activeB && !activeNext;

    // ---- phase 1: masks + numerator per half ----
    unsigned mwA[4], mwB[4];
    float numvA = 0.0f, numvB = 0.0f;
    #pragma unroll
    for (int r4 = 0; r4 < 4; r4++) {
        int t  = cA * CL + 32 * r4 + lane;
        int lt = lab[t];
        bool m = (msk[t] != 0) && (lt >= 0);
        mwA[r4] = __ballot_sync(0xffffffffu, m);
        if (m && t > 0) {
            int lp = lab[t - 1];
            numvA += __ldg(&trans[(lp < 0 ? 0 : lp) * KK + lt]) + emb[t * KK + lt];
        }
    }
    #pragma unroll
    for (int r4 = 0; r4 < 4; r4++) {
        int t  = cB * CL + 32 * r4 + lane;
        int lt = lab[t];
        bool m = (msk[t] != 0) && (lt >= 0);
        mwB[r4] = __ballot_sync(0xffffffffu, m);
        if (m) {
            int lp = lab[t - 1];
            numvB += __ldg(&trans[(lp < 0 ? 0 : lp) * KK + lt]) + emb[t * KK + lt];
        }
    }
    #pragma unroll
    for (int o = 16; o; o >>= 1) {
        numvA += __shfl_xor_sync(0xffffffffu, numvA, o);
        numvB += __shfl_xor_sync(0xffffffffu, numvB, o);
    }
    if (containsA) {   // last masked step lives in chunk cA
        int li;
        if      (mwA[3]) li = cA * CL + 96 + (31 - __clz(mwA[3]));
        else if (mwA[2]) li = cA * CL + 64 + (31 - __clz(mwA[2]));
        else if (mwA[1]) li = cA * CL + 32 + (31 - __clz(mwA[1]));
        else             li = cA * CL +      (31 - __clz(mwA[0]));
        int ll = lab[li];
        numvA += endT[ll < 0 ? 0 : ll];
    }
    if (containsB) {
        int li;
        if      (mwB[3]) li = cB * CL + 96 + (31 - __clz(mwB[3]));
        else if (mwB[2]) li = cB * CL + 64 + (31 - __clz(mwB[2]));
        else if (mwB[1]) li = cB * CL + 32 + (31 - __clz(mwB[1]));
        else             li = cB * CL +      (31 - __clz(mwB[0]));
        int ll = lab[li];
        numvB += endT[ll < 0 ? 0 : ll];
    }
    if (p == 0) {
        int l0 = lab[0];
        int l0c = (l0 < 0) ? 0 : l0;
        numvA += startT[l0c] + emb[l0c];
    }

    // packed exp(transitions) column (same weight both halves)
    ull wp[KK];
    #pragma unroll
    for (int i = 0; i < KK; i++) {
        float wv = (lane < KK) ? __expf(__ldg(&trans[i * KK + lane])) : 0.0f;
        wp[i] = packf2(wv, wv);
    }

    // ---- alpha init per half ----
    float aA, aB, MA = 0.0f, MB = 0.0f, baseA = 0.0f, baseB = 0.0f;
    if (p == 0) {
        float al = (lane < KK) ? (startT[lane] + emb[lane]) : -1e30f;
        float mx = al;
        #pragma unroll
        for (int o = 16; o; o >>= 1)
            mx = fmaxf(mx, __shfl_xor_sync(0xffffffffu, mx, o));
        MA = mx;
        aA = (lane < KK) ? __expf(al - mx) : 0.0f;
    } else {
        aA = (lane < KK) ? 1.0f : 0.0f;     // warm-up start
    }
    aB = (lane < KK) ? 1.0f : 0.0f;

    // tile schedule (16-step tiles; chunk c owns tiles 8c..8c+7, warm-up 8c-1)
    // half A: p==0 -> dummy round 0 (mask 0), tiles 0..7 in rounds 1..8
    #define TILE_A(r) ((p == 0) ? (((r) == 0) ? 0 : ((r) - 1)) : (16 * p - 1 + (r)))
    #define TILE_B(r) (16 * p + 7 + (r))

    load_tile(ebuf[wid][0][0], emb + (size_t)TILE_A(0) * TILEF, lane);
    load_tile(ebuf[wid][1][0], emb + (size_t)TILE_B(0) * TILEF, lane);
    CP_COMMIT();
    load_tile(ebuf[wid][0][1], emb + (size_t)TILE_A(1) * TILEF, lane);
    load_tile(ebuf[wid][1][1], emb + (size_t)TILE_B(1) * TILEF, lane);
    CP_COMMIT();

    int cur = 0;
    const int stoff = 2 * lane;

    for (int r = 0; r < 9; r++) {
        unsigned maskA, maskB;
        if (r == 0) {
            maskA = (p == 0) ? 0u : 0xFFFFu;          // warm-up fully in-mask
            maskB = activeB ? 0xFFFFu : 0u;
        } else {
            int jm = r - 1;
            maskA = (mwA[jm >> 1] >> (16 * (jm & 1))) & 0xFFFFu;
            maskB = (mwB[jm >> 1] >> (16 * (jm & 1))) & 0xFFFFu;
            if (p == 0 && jm == 0) maskA &= ~1u;      // t=0 is not a step
            if ((maskA | maskB) == 0u) break;         // prefix mask: done
        }

        CP_WAIT1();
        __syncwarp();
        const float* ebA = ebuf[wid][0][r & 1];
        const float* ebB = ebuf[wid][1][r & 1];

        #pragma unroll 8
        for (int tt = 0; tt < TSTEPS; ++tt) {
            float eA = ebA[tt * KK + lane];   // lanes>=17 read junk; unused
            float eB = ebB[tt * KK + lane];
            float gA = __expf(eA);
            float gB = __expf(eB);

            // broadcast both halves' alphas through shared memory
            *(float2*)&arow[wid][cur][stoff] = make_float2(aA, aB);
            __syncwarp();
            const ulonglong2* ap = (const ulonglong2*)&arow[wid][cur][0];
            ull u[KK];
            #pragma unroll
            for (int k = 0; k < 8; k++) {
                ulonglong2 q = ap[k];
                u[2 * k] = q.x;
                u[2 * k + 1] = q.y;
            }
            u[16] = *(const ull*)&arow[wid][cur][32];
            cur ^= 1;

            ull s0 = f32x2_fma(u[0], wp[0], 0ull);
            ull s1 = f32x2_fma(u[1], wp[1], 0ull);
            ull s2 = f32x2_fma(u[2], wp[2], 0ull);
            ull s3 = f32x2_fma(u[3], wp[3], 0ull);
            #pragma unroll
            for (int i = 4; i < 16; i += 4) {
                s0 = f32x2_fma(u[i],     wp[i],     s0);
                s1 = f32x2_fma(u[i + 1], wp[i + 1], s1);
                s2 = f32x2_fma(u[i + 2], wp[i + 2], s2);
                s3 = f32x2_fma(u[i + 3], wp[i + 3], s3);
            }
            s0 = f32x2_fma(u[16], wp[16], s0);
            const ull onep = 0x3f8000003f800000ull;   // (1.0f, 1.0f)
            ull s01 = f32x2_fma(s1, onep, s0);
            ull s23 = f32x2_fma(s3, onep, s2);
            ull s   = f32x2_fma(s23, onep, s01);

            float sA = lof(s), sB = hif(s);
            float anA = sA * gA;
            float anB = sB * gB;
            aA = ((maskA >> tt) & 1u) ? anA : aA;
            aB = ((maskB >> tt) & 1u) ? anB : aB;

            if ((tt & 7) == 0) {
                // renorm each half by exact power of two of max(prev alpha)
                float mA0 = lof(u[0]), mB0 = hif(u[0]);
                #pragma unroll
                for (int k = 1; k < KK; k++) {
                    mA0 = fmaxf(mA0, lof(u[k]));
                    mB0 = fmaxf(mB0, hif(u[k]));
                }
                int eA2 = (__float_as_int(mA0) >> 23) - 127;
                int eB2 = (__float_as_int(mB0) >> 23) - 127;
                aA *= __int_as_float((127 - eA2) << 23);
                aB *= __int_as_float((127 - eB2) << 23);
                MA += (float)eA2 * 0.6931471805599453f;
                MB += (float)eB2 * 0.6931471805599453f;
            }
        }

        if (r == 0) {
            // warm-up snapshot: base = log n(alpha at chunk start)
            float zsA = aA, zsB = aB;
            #pragma unroll
            for (int o = 16; o; o >>= 1) {
                zsA += __shfl_xor_sync(0xffffffffu, zsA, o);
                zsB += __shfl_xor_sync(0xffffffffu, zsB, o);
            }
            if (p > 0)    baseA = MA + __logf(zsA);
            if (activeB)  baseB = MB + __logf(zsB);
        }

        if (r + 2 <= 8) {
            load_tile(ebuf[wid][0][r & 1], emb + (size_t)TILE_A(r + 2) * TILEF, lane);
            load_tile(ebuf[wid][1][r & 1], emb + (size_t)TILE_B(r + 2) * TILEF, lane);
        }
        CP_COMMIT();
    }

    // ---- chunk contributions ----
    float zA = (lane < KK) ? (containsA ? aA * __expf(endT[lane]) : aA) : 0.0f;
    float zB = (lane < KK) ? (containsB ? aB * __expf(endT[lane]) : aB) : 0.0f;
    #pragma unroll
    for (int o = 16; o; o >>= 1) {
        zA += __shfl_xor_sync(0xffffffffu, zA, o);
        zB += __shfl_xor_sync(0xffffffffu, zB, o);
    }
    float finA = MA + __logf(zA);
    float finB = MB + __logf(zB);

    if (lane == 0) {
        g_part2[b * CHUNKS + cA] = (finA - baseA) - numvA;
        g_part2[b * CHUNKS + cB] = activeB ? ((finB - baseB) - numvB) : 0.0f;
    }
}

__global__ void reduce_kernel(float* __restrict__ out)
{
    __shared__ float sh[256];
    int t = threadIdx.x;
    float v = 0.0f;
    #pragma unroll
    for (int i = 0; i < (BB * CHUNKS) / 256; i++)
        v += g_part2[t + 256 * i];
    sh[t] = v;
    __syncthreads();
    #pragma unroll
    for (int s2 = 128; s2; s2 >>= 1) {
        if (t < s2) sh[t] += sh[t + s2];
        __syncthreads();
    }
    if (t == 0) out[0] = sh[0] * (1.0f / (float)BB);
}

extern "C" void kernel_launch(void* const* d_in, const int* in_sizes, int n_in,
                              void* d_out, int out_size)
{
    const float* em  = (const float*)d_in[0];
    const float* st  = (const float*)d_in[1];
    const float* en  = (const float*)d_in[2];
    const float* tr  = (const float*)d_in[3];
    const int*   lab = (const int*)d_in[4];
    const int*   att = (const int*)d_in[5];
    float* out = (float*)d_out;

    int copy = (out_size > in_sizes[0]) ? 1 : 0;

    crf_kernel<<<NCOPY_BLOCKS + NSCAN_BLOCKS, 128>>>(em, st, en, tr, lab, att, out, copy);
    reduce_kernel<<<1, 256>>>(out);
}

// round 9
// speedup vs baseline: 1.3195x; 1.3195x over previous
#include <cuda_runtime.h>

// Problem constants (B, S, K) = (512, 2048, 17)
#define BB 512
#define SS 2048
#define KK 17
#define SK (SS * KK)
#define CHUNKS 16
#define CL 128              // steps owned per chunk
#define TSTEPS 16           // steps per emission tile
#define TILEF (TSTEPS * KK) // 272 floats per tile
#define SCAN_WPB 8
#define NCOPY_BLOCKS 512
#define NSCAN_BLOCKS ((BB * CHUNKS) / SCAN_WPB)   // 1024

__device__ float g_part2[BB * CHUNKS];   // per-(seq,chunk) loss contribution

__device__ __forceinline__ void cp16(void* smem, const void* gmem) {
    unsigned s = (unsigned)__cvta_generic_to_shared(smem);
    asm volatile("cp.async.cg.shared.global [%0], [%1], 16;\n" :: "r"(s), "l"(gmem));
}
#define CP_COMMIT() asm volatile("cp.async.commit_group;\n" ::: "memory")
#define CP_WAIT1()  asm volatile("cp.async.wait_group 1;\n" ::: "memory")
#define CP_WAIT0()  asm volatile("cp.async.wait_group 0;\n" ::: "memory")

// one 272-float tile (68 x 16B) global -> shared via cp.async
__device__ __forceinline__ void load_tile(float* dst, const float* src, int lane) {
    cp16(dst + lane * 4,        src + lane * 4);
    cp16(dst + (32 + lane) * 4, src + (32 + lane) * 4);
    if (lane < 4)
        cp16(dst + (64 + lane) * 4, src + (64 + lane) * 4);
}

// one forward step given broadcast row ar; returns new (unselected) alpha and
// does the every-8 renorm bookkeeping.
#define STEP_BODY(DO_SELECT)                                                   \
    {                                                                          \
        float e = eb[tt * KK + lane];                                          \
        float gg = __expf(e);                                                  \
        arow[wid][lane] = a;                                                   \
        __syncwarp();                                                          \
        const float* ar = arow[wid];                                           \
        float4 v0 = *(const float4*)&ar[0];                                    \
        float4 v1 = *(const float4*)&ar[4];                                    \
        float4 v2 = *(const float4*)&ar[8];                                    \
        float4 v3 = *(const float4*)&ar[12];                                   \
        float  v16 = ar[16];                                                   \
        float s0 = v0.x * w[0];                                                \
        float s1 = v0.y * w[1];                                                \
        float s2 = v0.z * w[2];                                                \
        float s3 = v0.w * w[3];                                                \
        s0 = fmaf(v1.x, w[4],  s0);                                            \
        s1 = fmaf(v1.y, w[5],  s1);                                            \
        s2 = fmaf(v1.z, w[6],  s2);                                            \
        s3 = fmaf(v1.w, w[7],  s3);                                            \
        s0 = fmaf(v2.x, w[8],  s0);                                            \
        s1 = fmaf(v2.y, w[9],  s1);                                            \
        s2 = fmaf(v2.z, w[10], s2);                                            \
        s3 = fmaf(v2.w, w[11], s3);                                            \
        s0 = fmaf(v3.x, w[12], s0);                                            \
        s1 = fmaf(v3.y, w[13], s1);                                            \
        s2 = fmaf(v3.z, w[14], s2);                                            \
        s3 = fmaf(v3.w, w[15], s3);                                            \
        s0 = fmaf(v16,  w[16], s0);                                            \
        float s = (s0 + s1) + (s2 + s3);                                       \
        float anew = s * gg;                                                   \
        if (DO_SELECT) { bool m = (mw >> tt) & 1u; a = m ? anew : a; }         \
        else           { a = anew; }                                           \
        if ((tt & 7) == 0) {                                                   \
            float m0 = fmaxf(fmaxf(v0.x, v0.y), fmaxf(v0.z, v0.w));            \
            float m1 = fmaxf(fmaxf(v1.x, v1.y), fmaxf(v1.z, v1.w));            \
            float m2 = fmaxf(fmaxf(v2.x, v2.y), fmaxf(v2.z, v2.w));            \
            float m3 = fmaxf(fmaxf(v3.x, v3.y), fmaxf(v3.z, v3.w));            \
            float mx = fmaxf(fmaxf(m0, m1), fmaxf(fmaxf(m2, m3), v16));        \
            int e2 = (__float_as_int(mx) >> 23) - 127;                         \
            float scale = __int_as_float((127 - e2) << 23);                    \
            a *= scale;                                                        \
            M += (float)e2 * 0.6931471805599453f;                              \
        }                                                                      \
    }

__global__ __launch_bounds__(256) void crf_kernel(
    const float* __restrict__ em,      // [B,S,K]
    const float* __restrict__ startT,  // [K]
    const float* __restrict__ endT,    // [K]
    const float* __restrict__ trans,   // [K,K]
    const int*   __restrict__ labels,  // [B,S]
    const int*   __restrict__ attn,    // [B,S]
    float* __restrict__ out,           // [0]=loss, [1..]=emissions copy
    int copy_emissions)
{
    // ======== copy blocks: rotated, vectorized both sides ========
    if (blockIdx.x < NCOPY_BLOCKS) {
        if (!copy_emissions) return;
        const size_t base = (size_t)blockIdx.x * SK;
        const float4* s4 = (const float4*)(em + base);
        float* dst = out + 1 + base;           // dst+3 is 16B-aligned
        const int n4 = (SK - 4) / 4;           // 8703 aligned float4 stores
        for (int j = threadIdx.x; j < n4; j += 256) {
            float4 x = s4[j];
            float4 y = s4[j + 1];              // overlapping load: L1 hit
            *(float4*)(dst + 3 + 4 * j) = make_float4(x.w, y.x, y.y, y.z);
        }
        if (threadIdx.x == 0) {
            float4 x0 = s4[0];
            dst[0] = x0.x; dst[1] = x0.y; dst[2] = x0.z;
            dst[SK - 1] = em[base + SK - 1];
        }
        return;
    }

    // ======== scan blocks: 8 warps, each = one (sequence, chunk) ========
    const int tid  = threadIdx.x;
    const int wid  = tid >> 5;
    const int lane = tid & 31;
    const int gw   = (blockIdx.x - NCOPY_BLOCKS) * SCAN_WPB + wid;
    const int b    = gw / CHUNKS;
    const int c    = gw % CHUNKS;

    const float* emb = em + (size_t)b * SK;
    const int*   lab = labels + (size_t)b * SS;
    const int*   msk = attn   + (size_t)b * SS;

    __shared__ __align__(16) float ebuf[SCAN_WPB][2][TILEF];
    __shared__ __align__(16) float arow[SCAN_WPB][32];

    // ---- phase 1: masks + numerator for steps t in [c*CL, (c+1)*CL) ----
    const int tbase = c * CL;
    unsigned mwords[4];
    float numv = 0.0f;
    #pragma unroll
    for (int r = 0; r < 4; r++) {
        int t  = tbase + 32 * r + lane;
        int lt = lab[t];
        bool m = (msk[t] != 0) && (lt >= 0);
        mwords[r] = __ballot_sync(0xffffffffu, m);
        if (m && t > 0) {
            int lp  = lab[t - 1];
            int lpc = (lp < 0) ? 0 : lp;
            numv += __ldg(&trans[lpc * KK + lt]) + emb[t * KK + lt];
        }
    }
    #pragma unroll
    for (int o = 16; o; o >>= 1)
        numv += __shfl_xor_sync(0xffffffffu, numv, o);

    // active: chunk has any owned step in-mask (mask is a prefix)
    bool active = (c == 0) || ((mwords[0] & 1u) != 0);
    if (!active) {
        if (lane == 0) g_part2[gw] = 0.0f;
        return;
    }

    // contains the global last masked index?
    bool mnext = false;
    if (c < CHUNKS - 1) {
        int t = (c + 1) * CL;
        mnext = (msk[t] != 0) && (lab[t] >= 0);
    }
    const bool contains = !mnext;

    if (contains) {   // numerator end term (uniform across lanes)
        int li = 0;
        if      (mwords[3]) li = tbase + 96 + (31 - __clz(mwords[3]));
        else if (mwords[2]) li = tbase + 64 + (31 - __clz(mwords[2]));
        else if (mwords[1]) li = tbase + 32 + (31 - __clz(mwords[1]));
        else if (mwords[0]) li = tbase +      (31 - __clz(mwords[0]));
        int ll = lab[li];
        numv += endT[(ll < 0) ? 0 : ll];
    }
    if (c == 0) {
        int l0  = lab[0];
        int l0c = (l0 < 0) ? 0 : l0;
        numv += startT[l0c] + emb[l0c];
    }

    // exp(transitions) column for this lane's state
    float w[KK];
    #pragma unroll
    for (int i = 0; i < KK; i++)
        w[i] = (lane < KK) ? __expf(__ldg(&trans[i * KK + lane])) : 0.0f;

    // ---- alpha init ----
    float a, M;
    if (c == 0) {
        float al = (lane < KK) ? (startT[lane] + emb[lane]) : -1e30f;
        M = al;
        #pragma unroll
        for (int o = 16; o; o >>= 1)
            M = fmaxf(M, __shfl_xor_sync(0xffffffffu, M, o));
        a = (lane < KK) ? __expf(al - M) : 0.0f;
    } else {
        a = (lane < KK) ? 1.0f : 0.0f;     // uniform warm-up start
        M = 0.0f;
    }
    float base = 0.0f;                      // chunk 0: absolute reference

    // tile schedule: c==0 -> tiles 0..7 (steps 0..127, step 0 masked off)
    //                c>=1 -> tiles 8c-1 .. 8c+7 (16 warm-up + 128 owned steps)
    const int k0     = (c == 0) ? 0 : 8 * c - 1;
    const int ntiles = (c == 0) ? 8 : 9;

    load_tile(ebuf[wid][0], emb + (size_t)k0 * TILEF, lane);
    CP_COMMIT();
    load_tile(ebuf[wid][1], emb + (size_t)(k0 + 1) * TILEF, lane);
    CP_COMMIT();

    for (int j = 0; j < ntiles; j++) {
        const bool wutile = (c > 0) && (j == 0);
        unsigned mw;
        if (wutile) {
            mw = 0xFFFFu;                            // warm-up: fully in-mask
        } else {
            int jm = (c > 0) ? j - 1 : j;            // owned-tile index 0..7
            mw = (mwords[jm >> 1] >> (16 * (jm & 1))) & 0xFFFFu;
            if (c == 0 && jm == 0) mw &= ~1u;        // t=0 is not a step
            if (mw == 0u) {                          // prefix mask: done
                CP_WAIT0();                          // drain pending groups
                break;
            }
        }

        CP_WAIT1();
        __syncwarp();
        const float* eb = ebuf[wid][j & 1];

        if (mw == 0xFFFFu) {
            // fast path: every step in-mask, no select
            #pragma unroll 8
            for (int tt = 0; tt < TSTEPS; ++tt)
                STEP_BODY(0)
        } else {
            #pragma unroll 8
            for (int tt = 0; tt < TSTEPS; ++tt)
                STEP_BODY(1)
        }

        if (wutile) {
            // snapshot: base = log n(alpha at chunk start), n = sum
            float zs = a;
            #pragma unroll
            for (int o = 16; o; o >>= 1)
                zs += __shfl_xor_sync(0xffffffffu, zs, o);
            base = M + __logf(zs);
        }

        if (j + 2 < ntiles)
            load_tile(ebuf[wid][j & 1], emb + (size_t)(k0 + j + 2) * TILEF, lane);
        CP_COMMIT();
    }

    // ---- chunk contribution ----
    float zterm = (lane < KK) ? (contains ? a * __expf(endT[lane]) : a) : 0.0f;
    #pragma unroll
    for (int o = 16; o; o >>= 1)
        zterm += __shfl_xor_sync(0xffffffffu, zterm, o);
    float fin = M + __logf(zterm);

    if (lane == 0)
        g_part2[gw] = (fin - base) - numv;
}

__global__ void reduce_kernel(float* __restrict__ out)
{
    __shared__ float sh[256];
    int t = threadIdx.x;
    float v = 0.0f;
    #pragma unroll
    for (int i = 0; i < (BB * CHUNKS) / 256; i++)
        v += g_part2[t + 256 * i];
    sh[t] = v;
    __syncthreads();
    #pragma unroll
    for (int s2 = 128; s2; s2 >>= 1) {
        if (t < s2) sh[t] += sh[t + s2];
        __syncthreads();
    }
    if (t == 0) out[0] = sh[0] * (1.0f / (float)BB);
}

extern "C" void kernel_launch(void* const* d_in, const int* in_sizes, int n_in,
                              void* d_out, int out_size)
{
    const float* em  = (const float*)d_in[0];
    const float* st  = (const float*)d_in[1];
    const float* en  = (const float*)d_in[2];
    const float* tr  = (const float*)d_in[3];
    const int*   lab = (const int*)d_in[4];
    const int*   att = (const int*)d_in[5];
    float* out = (float*)d_out;

    int copy = (out_size > in_sizes[0]) ? 1 : 0;

    crf_kernel<<<NCOPY_BLOCKS + NSCAN_BLOCKS, 256>>>(em, st, en, tr, lab, att, out, copy);
    reduce_kernel<<<1, 256>>>(out);
}

// round 10
// speedup vs baseline: 1.3773x; 1.0438x over previous
#include <cuda_runtime.h>

// Problem constants (B, S, K) = (512, 2048, 17)
#define BB 512
#define SS 2048
#define KK 17
#define SK (SS * KK)
#define CHUNKS 32
#define CL 64               // steps owned per chunk
#define WU 8                // warm-up steps
#define TSTEPS 16           // steps per emission tile
#define TILEF (TSTEPS * KK) // 272 floats per tile
#define SCAN_WPB 8
#define NCOPY_BLOCKS 512
#define NSCAN_BLOCKS ((BB * CHUNKS) / SCAN_WPB)   // 2048

__device__ float g_part2[BB * CHUNKS];   // per-(seq,chunk) loss contribution

__device__ __forceinline__ void cp16(void* smem, const void* gmem) {
    unsigned s = (unsigned)__cvta_generic_to_shared(smem);
    asm volatile("cp.async.cg.shared.global [%0], [%1], 16;\n" :: "r"(s), "l"(gmem));
}
#define CP_COMMIT() asm volatile("cp.async.commit_group;\n" ::: "memory")
#define CP_WAIT1()  asm volatile("cp.async.wait_group 1;\n" ::: "memory")
#define CP_WAIT0()  asm volatile("cp.async.wait_group 0;\n" ::: "memory")

// one 272-float tile (68 x 16B) global -> shared via cp.async
__device__ __forceinline__ void load_tile(float* dst, const float* src, int lane) {
    cp16(dst + lane * 4,        src + lane * 4);
    cp16(dst + (32 + lane) * 4, src + (32 + lane) * 4);
    if (lane < 4)
        cp16(dst + (64 + lane) * 4, src + (64 + lane) * 4);
}

// one unmasked forward step (all in-mask); renorm bookkeeping every 8 steps
#define STEP_ONCE(tt)                                                          \
    {                                                                          \
        float e = eb[(tt) * KK + lane];                                        \
        float gg = __expf(e);                                                  \
        arow[wid][lane] = a;                                                   \
        __syncwarp();                                                          \
        const float* ar = arow[wid];                                           \
        float4 v0 = *(const float4*)&ar[0];                                    \
        float4 v1 = *(const float4*)&ar[4];                                    \
        float4 v2 = *(const float4*)&ar[8];                                    \
        float4 v3 = *(const float4*)&ar[12];                                   \
        float  v16 = ar[16];                                                   \
        float s0 = v0.x * w[0];                                                \
        float s1 = v0.y * w[1];                                                \
        float s2 = v0.z * w[2];                                                \
        float s3 = v0.w * w[3];                                                \
        s0 = fmaf(v1.x, w[4],  s0);                                            \
        s1 = fmaf(v1.y, w[5],  s1);                                            \
        s2 = fmaf(v1.z, w[6],  s2);                                            \
        s3 = fmaf(v1.w, w[7],  s3);                                            \
        s0 = fmaf(v2.x, w[8],  s0);                                            \
        s1 = fmaf(v2.y, w[9],  s1);                                            \
        s2 = fmaf(v2.z, w[10], s2);                                            \
        s3 = fmaf(v2.w, w[11], s3);                                            \
        s0 = fmaf(v3.x, w[12], s0);                                            \
        s1 = fmaf(v3.y, w[13], s1);                                            \
        s2 = fmaf(v3.z, w[14], s2);                                            \
        s3 = fmaf(v3.w, w[15], s3);                                            \
        s0 = fmaf(v16,  w[16], s0);                                            \
        float s = (s0 + s1) + (s2 + s3);                                       \
        a = s * gg;                                                            \
        if (((tt) & 7) == 0) {                                                 \
            float m0 = fmaxf(fmaxf(v0.x, v0.y), fmaxf(v0.z, v0.w));            \
            float m1 = fmaxf(fmaxf(v1.x, v1.y), fmaxf(v1.z, v1.w));            \
            float m2 = fmaxf(fmaxf(v2.x, v2.y), fmaxf(v2.z, v2.w));            \
            float m3 = fmaxf(fmaxf(v3.x, v3.y), fmaxf(v3.z, v3.w));            \
            float mx = fmaxf(fmaxf(m0, m1), fmaxf(fmaxf(m2, m3), v16));        \
            int e2 = (__float_as_int(mx) >> 23) - 127;                         \
            float scale = __int_as_float((127 - e2) << 23);                    \
            a *= scale;                                                        \
            M += (float)e2 * 0.6931471805599453f;                              \
        }                                                                      \
    }

__global__ __launch_bounds__(256) void crf_kernel(
    const float* __restrict__ em,      // [B,S,K]
    const float* __restrict__ startT,  // [K]
    const float* __restrict__ endT,    // [K]
    const float* __restrict__ trans,   // [K,K]
    const int*   __restrict__ labels,  // [B,S]
    const int*   __restrict__ attn,    // [B,S]
    float* __restrict__ out,           // [0]=loss, [1..]=emissions copy
    int copy_emissions)
{
    // ======== copy blocks: rotated, vectorized both sides ========
    if (blockIdx.x < NCOPY_BLOCKS) {
        if (!copy_emissions) return;
        const size_t base = (size_t)blockIdx.x * SK;
        const float4* s4 = (const float4*)(em + base);
        float* dst = out + 1 + base;           // dst+3 is 16B-aligned
        const int n4 = (SK - 4) / 4;           // 8703 aligned float4 stores
        for (int j = threadIdx.x; j < n4; j += 256) {
            float4 x = s4[j];
            float4 y = s4[j + 1];              // overlapping load: L1 hit
            *(float4*)(dst + 3 + 4 * j) = make_float4(x.w, y.x, y.y, y.z);
        }
        if (threadIdx.x == 0) {
            float4 x0 = s4[0];
            dst[0] = x0.x; dst[1] = x0.y; dst[2] = x0.z;
            dst[SK - 1] = em[base + SK - 1];
        }
        return;
    }

    // ======== scan blocks: 8 warps, each = one (sequence, chunk) ========
    const int tid  = threadIdx.x;
    const int wid  = tid >> 5;
    const int lane = tid & 31;
    const int gw   = (blockIdx.x - NCOPY_BLOCKS) * SCAN_WPB + wid;
    const int b    = gw / CHUNKS;
    const int c    = gw % CHUNKS;

    const float* emb = em + (size_t)b * SK;
    const int*   lab = labels + (size_t)b * SS;
    const int*   msk = attn   + (size_t)b * SS;

    __shared__ __align__(16) float ebuf[SCAN_WPB][2][TILEF];
    __shared__ __align__(16) float arow[SCAN_WPB][32];

    // ---- phase 1: masks + numerator for steps t in [c*CL, (c+1)*CL) ----
    const int tbase = c * CL;
    unsigned mwords[2];
    float numv = 0.0f;
    #pragma unroll
    for (int r = 0; r < 2; r++) {
        int t  = tbase + 32 * r + lane;
        int lt = lab[t];
        bool m = (msk[t] != 0) && (lt >= 0);
        mwords[r] = __ballot_sync(0xffffffffu, m);
        if (m && t > 0) {
            int lp  = lab[t - 1];
            int lpc = (lp < 0) ? 0 : lp;
            numv += __ldg(&trans[lpc * KK + lt]) + emb[t * KK + lt];
        }
    }
    #pragma unroll
    for (int o = 16; o; o >>= 1)
        numv += __shfl_xor_sync(0xffffffffu, numv, o);

    // active: chunk has any owned step in-mask (mask is a prefix)
    bool active = (c == 0) || ((mwords[0] & 1u) != 0);
    if (!active) {
        if (lane == 0) g_part2[gw] = 0.0f;
        return;
    }

    // does this chunk contain the global last masked index?
    bool mnext = false;
    if (c < CHUNKS - 1) {
        int t = (c + 1) * CL;
        mnext = (msk[t] != 0) && (lab[t] >= 0);
    }
    const bool contains = !mnext;

    if (contains) {   // numerator end term (uniform across lanes)
        int li;
        if (mwords[1]) li = tbase + 32 + (31 - __clz(mwords[1]));
        else           li = tbase +      (31 - __clz(mwords[0]));
        int ll = lab[li];
        numv += endT[(ll < 0) ? 0 : ll];
    }
    if (c == 0) {
        int l0  = lab[0];
        int l0c = (l0 < 0) ? 0 : l0;
        numv += startT[l0c] + emb[l0c];
    }

    // exp(transitions) column for this lane's state
    float w[KK];
    #pragma unroll
    for (int i = 0; i < KK; i++)
        w[i] = (lane < KK) ? __expf(__ldg(&trans[i * KK + lane])) : 0.0f;

    // ---- alpha init ----
    float a, M;
    if (c == 0) {
        float al = (lane < KK) ? (startT[lane] + emb[lane]) : -1e30f;
        M = al;
        #pragma unroll
        for (int o = 16; o; o >>= 1)
            M = fmaxf(M, __shfl_xor_sync(0xffffffffu, M, o));
        a = (lane < KK) ? __expf(al - M) : 0.0f;
    } else {
        a = (lane < KK) ? 1.0f : 0.0f;     // uniform warm-up start
        M = 0.0f;
    }
    float base = 0.0f;                      // chunk 0: absolute reference

    // tile schedule: chunk c owns tiles 4c..4c+3 (64 steps).
    // c>0: round 0 = warm-up (last 8 steps of tile 4c-1), rounds 1..4 owned.
    // c==0: rounds 0..3 owned (tile 0 starts at step 1).
    const int k0 = (c == 0) ? 0 : 4 * c - 1;
    const int nr = (c == 0) ? 4 : 5;

    load_tile(ebuf[wid][0], emb + (size_t)k0 * TILEF, lane);
    CP_COMMIT();
    load_tile(ebuf[wid][1], emb + (size_t)(k0 + 1) * TILEF, lane);
    CP_COMMIT();

    for (int j = 0; j < nr; j++) {
        CP_WAIT1();
        __syncwarp();
        const float* eb = ebuf[wid][j & 1];

        if (c > 0 && j == 0) {
            // warm-up: steps 8..15 of tile 4c-1, all in-mask (prefix)
            #pragma unroll
            for (int tt = WU; tt < TSTEPS; ++tt)
                STEP_ONCE(tt)
            // snapshot: base = log n(alpha at chunk start)
            float zs = a;
            #pragma unroll
            for (int o = 16; o; o >>= 1)
                zs += __shfl_xor_sync(0xffffffffu, zs, o);
            base = M + __logf(zs);
        } else {
            const int jm = (c > 0) ? j - 1 : j;      // owned-tile index 0..3
            unsigned mw = (mwords[jm >> 1] >> (16 * (jm & 1))) & 0xFFFFu;
            int tt0 = 0;
            if (c == 0 && jm == 0) { mw &= ~1u; tt0 = 1; }
            const int nst = __popc(mw);              // mask is a prefix
            if (nst == TSTEPS - tt0 && tt0 == 0) {
                #pragma unroll
                for (int tt = 0; tt < TSTEPS; ++tt)
                    STEP_ONCE(tt)
            } else {
                for (int tt = tt0; tt < tt0 + nst; ++tt)
                    STEP_ONCE(tt)
                if (nst < TSTEPS - tt0) {            // boundary tile: done
                    CP_WAIT0();
                    break;
                }
            }
        }

        if (j + 2 < nr)
            load_tile(ebuf[wid][j & 1], emb + (size_t)(k0 + j + 2) * TILEF, lane);
        CP_COMMIT();
    }

    // ---- chunk contribution ----
    float zterm = (lane < KK) ? (contains ? a * __expf(endT[lane]) : a) : 0.0f;
    #pragma unroll
    for (int o = 16; o; o >>= 1)
        zterm += __shfl_xor_sync(0xffffffffu, zterm, o);
    float fin = M + __logf(zterm);

    if (lane == 0)
        g_part2[gw] = (fin - base) - numv;
}

__global__ void reduce_kernel(float* __restrict__ out)
{
    __shared__ float sh[256];
    int t = threadIdx.x;
    float v = 0.0f;
    #pragma unroll
    for (int i = 0; i < (BB * CHUNKS) / 256; i++)
        v += g_part2[t + 256 * i];
    sh[t] = v;
    __syncthreads();
    #pragma unroll
    for (int s2 = 128; s2; s2 >>= 1) {
        if (t < s2) sh[t] += sh[t + s2];
        __syncthreads();
    }
    if (t == 0) out[0] = sh[0] * (1.0f / (float)BB);
}

extern "C" void kernel_launch(void* const* d_in, const int* in_sizes, int n_in,
                              void* d_out, int out_size)
{
    const float* em  = (const float*)d_in[0];
    const float* st  = (const float*)d_in[1];
    const float* en  = (const float*)d_in[2];
    const float* tr  = (const float*)d_in[3];
    const int*   lab = (const int*)d_in[4];
    const int*   att = (const int*)d_in[5];
    float* out = (float*)d_out;

    int copy = (out_size > in_sizes[0]) ? 1 : 0;

    crf_kernel<<<NCOPY_BLOCKS + NSCAN_BLOCKS, 256>>>(em, st, en, tr, lab, att, out, copy);
    reduce_kernel<<<1, 256>>>(out);
}